// round 10
// baseline (speedup 1.0000x reference)
#include <cuda_runtime.h>
#include <cuda_bf16.h>
#include <cuda_fp16.h>
#include <mma.h>

using namespace nvcuda;

#define NN 50000
#define NPAD 50048            // multiple of 64
#define NE 800000             // divisible by 64
#define NG 500
#define HD 128
#define NB_SCAN 196           // ceil(50000/256)

// ---------------- static device scratch (allocation-free rule) ----------------
__device__ float d_h0[(size_t)NPAD * 128];
__device__ float d_h1[(size_t)NPAD * 128];
__device__ float d_G[(size_t)NPAD * 512];                  // [Af|Bf|As|Bs] per node
__device__ __half d_msg[(size_t)NE * 128];                 // CSR-ordered per-edge messages (fp16)
__device__ int d_cnt[NN];
__device__ int d_off[NN + 1];
__device__ int d_cur[NN];
__device__ int d_csr_src[NE];
__device__ int d_csr_dst[NE];
__device__ int d_csr_eid[NE];
__device__ int d_bsum[256];
__device__ float d_pool[NG * HD];
__device__ float d_cntf[NG];
__device__ float d_Wcat[3 * 128 * 512];
__device__ float d_bcat[3 * 512];
__device__ __nv_bfloat16 d_Wecat_h[32 * 768];

// ---------------- fast math ----------------
__device__ __forceinline__ float ex2f(float x) { float r; asm("ex2.approx.f32 %0, %1;" : "=f"(r) : "f"(x)); return r; }
__device__ __forceinline__ float lg2f(float x) { float r; asm("lg2.approx.f32 %0, %1;" : "=f"(r) : "f"(x)); return r; }
__device__ __forceinline__ float tanhf_(float x){ float r; asm("tanh.approx.f32 %0, %1;" : "=f"(r) : "f"(x)); return r; }
__device__ __forceinline__ float tf32r(float x) { float r; asm("cvt.rna.tf32.f32 %0, %1;" : "=f"(r) : "f"(x)); return r; }

#define LOG2E 1.4426950408889634f
#define LN2   0.6931471805599453f

__device__ __forceinline__ float msgf(float pf, float ps) {
    float sg = fmaf(0.5f, tanhf_(0.5f * pf), 0.5f);          // sigmoid, 1 MUFU
    float sp = LN2 * lg2f(1.0f + ex2f(ps * LOG2E));          // softplus, 2 MUFU
    sp = (ps > 15.0f) ? ps : sp;
    return sg * sp;
}

__device__ __forceinline__ void addm(float4& a, uint2 q) {
    float2 f0 = __half22float2(*(const __half2*)&q.x);
    float2 f1 = __half22float2(*(const __half2*)&q.y);
    a.x += f0.x; a.y += f0.y; a.z += f1.x; a.w += f1.y;
}

// ---------------- misc kernels ----------------
__global__ void zero_stats() {
    int i = blockIdx.x * blockDim.x + threadIdx.x;
    if (i < NG * HD) d_pool[i] = 0.0f;
    if (i < NG) d_cntf[i] = 0.0f;
    if (i < NN) d_cnt[i] = 0;
}

__global__ void repack_kernel(const float* __restrict__ Wf1, const float* __restrict__ Ws1,
                              const float* __restrict__ Wf2, const float* __restrict__ Ws2,
                              const float* __restrict__ Wf3, const float* __restrict__ Ws3,
                              const float* __restrict__ bf1, const float* __restrict__ bs1,
                              const float* __restrict__ bf2, const float* __restrict__ bs2,
                              const float* __restrict__ bf3, const float* __restrict__ bs3) {
    int idx = blockIdx.x * blockDim.x + threadIdx.x;
    const float* Wf[3] = {Wf1, Wf2, Wf3};
    const float* Ws[3] = {Ws1, Ws2, Ws3};
    if (idx < 3 * 128 * 512) {
        int l = idx / 65536;
        int rem = idx - l * 65536;
        int k = rem >> 9;
        int c = rem & 511;
        int g = c >> 7;            // 0 Af, 1 Bf, 2 As, 3 Bs
        int c0 = c & 127;
        float v;
        if (g == 0)      v = Wf[l][k * 128 + c0];
        else if (g == 1) v = Wf[l][(128 + k) * 128 + c0];
        else if (g == 2) v = Ws[l][k * 128 + c0];
        else             v = Ws[l][(128 + k) * 128 + c0];
        d_Wcat[idx] = v;
        return;
    }
    int idx2 = idx - 3 * 128 * 512;
    if (idx2 < 32 * 768) {
        // lane-interleaved: within each layer's 256 cols,
        // cols 8*li..8*li+3 = f channels 4li..4li+3; 8*li+4..8*li+7 = s channels 4li..4li+3
        int r = idx2 / 768;
        int c = idx2 - r * 768;
        int l = c >> 8;            // layer
        int w = c & 255;
        int li = w >> 3;           // lane
        int q = w & 7;
        int g = q >> 2;            // 0 f, 1 s
        int c0 = 4 * li + (q & 3);
        d_Wecat_h[idx2] = __float2bfloat16((g == 0 ? Wf[l] : Ws[l])[(256 + r) * 128 + c0]);
        return;
    }
    int idx3 = idx2 - 32 * 768;
    if (idx3 < 3 * 512) {
        int l = idx3 / 512;
        int c = idx3 - l * 512;
        int g = c >> 7;
        int c0 = c & 127;
        const float* bfp[3] = {bf1, bf2, bf3};
        const float* bsp[3] = {bs1, bs2, bs3};
        float v = (g == 0) ? bfp[l][c0] : ((g == 2) ? bsp[l][c0] : 0.0f);
        d_bcat[idx3] = v;
    }
}

__global__ void count_kernel(const int* __restrict__ dst) {
    int e = blockIdx.x * blockDim.x + threadIdx.x;
    if (e < NE) atomicAdd(&d_cnt[dst[e]], 1);
}

// ---- hierarchical scan ----
__device__ __forceinline__ int block_scan_incl(int v, int* wsum, int lane, int wid) {
    int x = v;
    #pragma unroll
    for (int o = 1; o < 32; o <<= 1) {
        int t = __shfl_up_sync(0xffffffffu, x, o);
        if (lane >= o) x += t;
    }
    if (lane == 31) wsum[wid] = x;
    __syncthreads();
    if (wid == 0) {
        int t2 = (lane < 8) ? wsum[lane] : 0;
        #pragma unroll
        for (int o = 1; o < 8; o <<= 1) {
            int t = __shfl_up_sync(0xffffffffu, t2, o);
            if (lane >= o) t2 += t;
        }
        if (lane < 8) wsum[lane] = t2;
    }
    __syncthreads();
    return x + (wid ? wsum[wid - 1] : 0);
}

__global__ void scan_blocks() {
    __shared__ int wsum[8];
    int lane = threadIdx.x & 31, wid = threadIdx.x >> 5;
    int i = blockIdx.x * 256 + threadIdx.x;
    int v = (i < NN) ? d_cnt[i] : 0;
    int incl = block_scan_incl(v, wsum, lane, wid);
    if (i < NN) d_off[i] = incl - v;
    if (threadIdx.x == 255) d_bsum[blockIdx.x] = incl;
}

__global__ void scan_top() {
    __shared__ int wsum[8];
    int lane = threadIdx.x & 31, wid = threadIdx.x >> 5;
    int t = threadIdx.x;
    int v = (t < NB_SCAN) ? d_bsum[t] : 0;
    int incl = block_scan_incl(v, wsum, lane, wid);
    if (t < NB_SCAN) d_bsum[t] = incl - v;
}

__global__ void scan_add() {
    int i = blockIdx.x * 256 + threadIdx.x;
    if (i < NN) {
        int o = d_off[i] + d_bsum[blockIdx.x];
        d_off[i] = o;
        d_cur[i] = o;
    }
    if (i == 0) d_off[NN] = NE;
}

__global__ void scatter_kernel(const int* __restrict__ src, const int* __restrict__ dst) {
    int e = blockIdx.x * blockDim.x + threadIdx.x;
    if (e < NE) {
        int d = dst[e];
        int p = atomicAdd(&d_cur[d], 1);
        d_csr_src[p] = src[e];
        d_csr_dst[p] = d;
        d_csr_eid[p] = e;
    }
}

__global__ void embed_kernel(const int* __restrict__ x, const float* __restrict__ emb) {
    int idx = blockIdx.x * blockDim.x + threadIdx.x;
    if (idx >= NN * 32) return;
    int n = idx >> 5, c4 = idx & 31;
    float4 v = ((const float4*)(emb + (size_t)x[n] * 128))[c4];
    ((float4*)(d_h0 + (size_t)n * 128))[c4] = v;
}

// ---------------- node GEMM: tf32 wmma ----------------
template <int K>
__global__ void __launch_bounds__(256)
gemm_tf32(const float* __restrict__ A, const float* __restrict__ B,
          const float* __restrict__ bias, float* __restrict__ C,
          int ldb, int ldc) {
    extern __shared__ float sm[];
    float (*As)[K + 4] = (float (*)[K + 4])sm;
    float (*Bs)[68]    = (float (*)[68])(sm + 64 * (K + 4));
    float (*Us)[68]    = (float (*)[68])(sm + 64 * (K + 4) + K * 68);

    int tid = threadIdx.x;
    size_t rowBase = (size_t)blockIdx.x * 64;
    int colBase = blockIdx.y * 64;

    constexpr int K4 = K / 4;
    for (int i = tid; i < 64 * K4; i += 256) {
        int r = i / K4, c = (i - r * K4) * 4;
        float4 v = *(const float4*)&A[(rowBase + r) * K + c];
        v.x = tf32r(v.x); v.y = tf32r(v.y); v.z = tf32r(v.z); v.w = tf32r(v.w);
        *(float4*)&As[r][c] = v;
    }
    for (int i = tid; i < K * 16; i += 256) {
        int r = i / 16, c = (i - r * 16) * 4;
        float4 v = *(const float4*)&B[(size_t)r * ldb + colBase + c];
        v.x = tf32r(v.x); v.y = tf32r(v.y); v.z = tf32r(v.z); v.w = tf32r(v.w);
        *(float4*)&Bs[r][c] = v;
    }
    __syncthreads();

    int warp = tid >> 5;
    int wm = warp >> 2, wn = warp & 3;

    wmma::fragment<wmma::accumulator, 16, 16, 8, float> c0, c1;
    wmma::fill_fragment(c0, 0.0f);
    wmma::fill_fragment(c1, 0.0f);

    #pragma unroll
    for (int k0 = 0; k0 < K; k0 += 8) {
        wmma::fragment<wmma::matrix_a, 16, 16, 8, wmma::precision::tf32, wmma::row_major> a0, a1;
        wmma::fragment<wmma::matrix_b, 16, 16, 8, wmma::precision::tf32, wmma::row_major> b;
        wmma::load_matrix_sync(a0, &As[wm * 32][k0], K + 4);
        wmma::load_matrix_sync(a1, &As[wm * 32 + 16][k0], K + 4);
        wmma::load_matrix_sync(b, &Bs[k0][wn * 16], 68);
        wmma::mma_sync(c0, a0, b, c0);
        wmma::mma_sync(c1, a1, b, c1);
    }
    wmma::store_matrix_sync(&Us[wm * 32][wn * 16], c0, 68, wmma::mem_row_major);
    wmma::store_matrix_sync(&Us[wm * 32 + 16][wn * 16], c1, 68, wmma::mem_row_major);
    __syncthreads();

    for (int i = tid; i < 1024; i += 256) {
        int r = i >> 4, c = (i & 15) << 2;
        float4 v = *(const float4*)&Us[r][c];
        float4 b4 = *(const float4*)&bias[colBase + c];
        v.x += b4.x; v.y += b4.y; v.z += b4.z; v.w += b4.w;
        *(float4*)&C[(rowBase + r) * (size_t)ldc + colBase + c] = v;
    }
}

// ---------------- fused edge kernel: e-projection wmma + gating + msg write ----------------
// smem: Bs bf16[32][264]=16896 | As bf16[64][40]=5120 | Us f32[64][264]=67584 | idx 3*64 int=768
#define FE_AS_OFF 16896
#define FE_US_OFF 22016
#define FE_IDX_OFF 89600
#define FE_SMEM 90368
__global__ void __launch_bounds__(256) fused_edge_kernel(const float* __restrict__ ea, int layer) {
    extern __shared__ char smraw[];
    __nv_bfloat16 (*Bs)[264] = (__nv_bfloat16 (*)[264])smraw;
    __nv_bfloat16 (*As)[40]  = (__nv_bfloat16 (*)[40])(smraw + FE_AS_OFF);
    float (*Us)[264]         = (float (*)[264])(smraw + FE_US_OFF);
    int* ssrc = (int*)(smraw + FE_IDX_OFF);
    int* sdst = ssrc + 64;
    int* seid = sdst + 64;

    int tid = threadIdx.x;
    size_t base = (size_t)blockIdx.x * 64;

    if (tid < 64) {
        ssrc[tid] = d_csr_src[base + tid];
        sdst[tid] = d_csr_dst[base + tid];
        seid[tid] = d_csr_eid[base + tid];
    }
    // B panel: layer's 32x256 bf16 slice (lane-interleaved cols)
    for (int i = tid; i < 1024; i += 256) {
        int r = i >> 5, c8 = (i & 31) * 8;
        *(uint4*)&Bs[r][c8] = *(const uint4*)&d_Wecat_h[r * 768 + layer * 256 + c8];
    }
    __syncthreads();
    // gather edge_attr rows via eid -> bf16
    for (int i = tid; i < 512; i += 256) {
        int r = i >> 3, c4 = (i & 7) * 4;
        float4 v = *(const float4*)(ea + (size_t)seid[r] * 32 + c4);
        *(__nv_bfloat162*)&As[r][c4]     = __float22bfloat162_rn(make_float2(v.x, v.y));
        *(__nv_bfloat162*)&As[r][c4 + 2] = __float22bfloat162_rn(make_float2(v.z, v.w));
    }
    __syncthreads();

    int w = tid >> 5, lane = tid & 31;
    {
        int wm = w >> 2, wn = w & 3;   // rows 32*wm.., cols 64*wn..
        wmma::fragment<wmma::accumulator, 16, 16, 16, float> acc[2][4];
        #pragma unroll
        for (int i = 0; i < 2; ++i)
            #pragma unroll
            for (int j = 0; j < 4; ++j)
                wmma::fill_fragment(acc[i][j], 0.0f);
        #pragma unroll
        for (int k0 = 0; k0 < 32; k0 += 16) {
            wmma::fragment<wmma::matrix_a, 16, 16, 16, __nv_bfloat16, wmma::row_major> a[2];
            wmma::fragment<wmma::matrix_b, 16, 16, 16, __nv_bfloat16, wmma::row_major> b[4];
            #pragma unroll
            for (int i = 0; i < 2; ++i)
                wmma::load_matrix_sync(a[i], &As[wm * 32 + i * 16][k0], 40);
            #pragma unroll
            for (int j = 0; j < 4; ++j)
                wmma::load_matrix_sync(b[j], &Bs[k0][wn * 64 + j * 16], 264);
            #pragma unroll
            for (int i = 0; i < 2; ++i)
                #pragma unroll
                for (int j = 0; j < 4; ++j)
                    wmma::mma_sync(acc[i][j], a[i], b[j], acc[i][j]);
        }
        #pragma unroll
        for (int i = 0; i < 2; ++i)
            #pragma unroll
            for (int j = 0; j < 4; ++j)
                wmma::store_matrix_sync(&Us[wm * 32 + i * 16][wn * 64 + j * 16], acc[i][j],
                                        264, wmma::mem_row_major);
    }
    __syncthreads();

    // message phase: warp w handles edges 8w..8w+7; lane handles channels 4l..4l+3
    float4 af = make_float4(0.f, 0.f, 0.f, 0.f);
    float4 as4 = make_float4(0.f, 0.f, 0.f, 0.f);
    int cur = -1;
    #pragma unroll
    for (int j = 0; j < 8; ++j) {
        int le = 8 * w + j;
        int dstj = sdst[le];
        int srcj = ssrc[le];
        if (dstj != cur) {
            const float4* Gd = (const float4*)(d_G + (size_t)dstj * 512);
            af = Gd[lane]; as4 = Gd[64 + lane]; cur = dstj;
        }
        const float4* Gs = (const float4*)(d_G + (size_t)srcj * 512);
        float4 bf = Gs[32 + lane];
        float4 bs = Gs[96 + lane];
        const float* u = &Us[le][8 * lane];
        float m0 = msgf(af.x + bf.x + u[0], as4.x + bs.x + u[4]);
        float m1 = msgf(af.y + bf.y + u[1], as4.y + bs.y + u[5]);
        float m2 = msgf(af.z + bf.z + u[2], as4.z + bs.z + u[6]);
        float m3 = msgf(af.w + bf.w + u[3], as4.w + bs.w + u[7]);
        __half2 p0 = __floats2half2_rn(m0, m1);
        __half2 p1 = __floats2half2_rn(m2, m3);
        uint2 pk;
        pk.x = *(unsigned*)&p0;
        pk.y = *(unsigned*)&p1;
        *(uint2*)(d_msg + (base + le) * 128 + 4 * lane) = pk;
    }
}

// ---------------- aggregation: warp per node, sequential msg stream ----------------
__global__ void __launch_bounds__(256) agg_kernel(int layer) {
    int n = blockIdx.x * 8 + (threadIdx.x >> 5);
    if (n >= NN) return;
    int lane = threadIdx.x & 31;
    const float* hin  = (layer == 1) ? d_h1 : d_h0;
    float*       hout = (layer == 1) ? d_h0 : d_h1;

    int beg = d_off[n], end = d_off[n + 1];
    const __half* M = d_msg + 4 * lane;
    float4 acc = make_float4(0.f, 0.f, 0.f, 0.f);
    int p = beg;
    for (; p + 4 <= end; p += 4) {
        uint2 q0 = *(const uint2*)(M + (size_t)p * 128);
        uint2 q1 = *(const uint2*)(M + (size_t)(p + 1) * 128);
        uint2 q2 = *(const uint2*)(M + (size_t)(p + 2) * 128);
        uint2 q3 = *(const uint2*)(M + (size_t)(p + 3) * 128);
        addm(acc, q0); addm(acc, q1); addm(acc, q2); addm(acc, q3);
    }
    for (; p < end; ++p) {
        uint2 q0 = *(const uint2*)(M + (size_t)p * 128);
        addm(acc, q0);
    }
    float4 h = ((const float4*)(hin + (size_t)n * 128))[lane];
    h.x = fmaxf(h.x + acc.x, 0.f);
    h.y = fmaxf(h.y + acc.y, 0.f);
    h.z = fmaxf(h.z + acc.z, 0.f);
    h.w = fmaxf(h.w + acc.w, 0.f);
    ((float4*)(hout + (size_t)n * 128))[lane] = h;
}

// ---------------- pooling ----------------
__global__ void pool_kernel(const float* __restrict__ h, const int* __restrict__ batch) {
    int t = threadIdx.x;
    int per = (NN + gridDim.x - 1) / gridDim.x;
    int n0 = blockIdx.x * per;
    int n1 = n0 + per; if (n1 > NN) n1 = NN;
    if (n0 >= n1) return;
    int g = batch[n0];
    float acc = 0.f, cnt = 0.f;
    for (int n = n0; n < n1; ++n) {
        int gn = batch[n];
        if (gn != g) {
            atomicAdd(&d_pool[g * 128 + t], acc);
            if (t == 0) atomicAdd(&d_cntf[g], cnt);
            acc = 0.f; cnt = 0.f; g = gn;
        }
        acc += h[(size_t)n * 128 + t];
        cnt += 1.f;
    }
    atomicAdd(&d_pool[g * 128 + t], acc);
    if (t == 0) atomicAdd(&d_cntf[g], cnt);
}

__global__ void final_kernel(const float* __restrict__ Wlin, const float* __restrict__ blin,
                             float* __restrict__ out) {
    __shared__ float pm[128];
    int gph = blockIdx.x, t = threadIdx.x;
    float inv = 1.0f / fmaxf(d_cntf[gph], 1.0f);
    pm[t] = d_pool[gph * 128 + t] * inv;
    __syncthreads();
    float s = blin[t];
    #pragma unroll 8
    for (int k = 0; k < 128; ++k) s += pm[k] * Wlin[k * 128 + t];
    out[gph * 128 + t] = s;
}

// ---------------- host ----------------
extern "C" void kernel_launch(void* const* d_in, const int* in_sizes, int n_in,
                              void* d_out, int out_size) {
    const int*   x     = (const int*)d_in[0];
    const int*   ei    = (const int*)d_in[1];
    const float* ea    = (const float*)d_in[2];
    const int*   batch = (const int*)d_in[3];
    const float* emb   = (const float*)d_in[4];
    const float* Wf1 = (const float*)d_in[5],  *bf1 = (const float*)d_in[6];
    const float* Ws1 = (const float*)d_in[7],  *bs1 = (const float*)d_in[8];
    const float* Wf2 = (const float*)d_in[9],  *bf2 = (const float*)d_in[10];
    const float* Ws2 = (const float*)d_in[11], *bs2 = (const float*)d_in[12];
    const float* Wf3 = (const float*)d_in[13], *bf3 = (const float*)d_in[14];
    const float* Ws3 = (const float*)d_in[15], *bs3 = (const float*)d_in[16];
    const float* Wlin = (const float*)d_in[17], *blin = (const float*)d_in[18];
    float* out = (float*)d_out;

    const int* src = ei;
    const int* dst = ei + NE;

    const int SMEM_NODE = (64 * 132 + 128 * 68 + 64 * 68) * 4;  // 86016
    cudaFuncSetAttribute(gemm_tf32<128>, cudaFuncAttributeMaxDynamicSharedMemorySize, SMEM_NODE);
    cudaFuncSetAttribute(fused_edge_kernel, cudaFuncAttributeMaxDynamicSharedMemorySize, FE_SMEM);

    void *p_h0, *p_h1, *p_G, *p_Wcat, *p_bcat;
    cudaGetSymbolAddress(&p_h0, d_h0);
    cudaGetSymbolAddress(&p_h1, d_h1);
    cudaGetSymbolAddress(&p_G, d_G);
    cudaGetSymbolAddress(&p_Wcat, d_Wcat);
    cudaGetSymbolAddress(&p_bcat, d_bcat);

    zero_stats<<<250, 256>>>();
    repack_kernel<<<(3 * 128 * 512 + 32 * 768 + 3 * 512 + 255) / 256, 256>>>(
        Wf1, Ws1, Wf2, Ws2, Wf3, Ws3, bf1, bs1, bf2, bs2, bf3, bs3);
    count_kernel<<<(NE + 255) / 256, 256>>>(dst);
    scan_blocks<<<NB_SCAN, 256>>>();
    scan_top<<<1, 256>>>();
    scan_add<<<NB_SCAN, 256>>>();
    scatter_kernel<<<(NE + 255) / 256, 256>>>(src, dst);
    embed_kernel<<<(NN * 32 + 255) / 256, 256>>>(x, emb);

    float* hbufs[3] = {(float*)p_h0, (float*)p_h1, (float*)p_h0};
    for (int l = 0; l < 3; ++l) {
        dim3 grid(NPAD / 64, 8);
        gemm_tf32<128><<<grid, 256, SMEM_NODE>>>(
            hbufs[l], (const float*)p_Wcat + l * 65536,
            (const float*)p_bcat + l * 512, (float*)p_G, 512, 512);
        fused_edge_kernel<<<NE / 64, 256, FE_SMEM>>>(ea, l);
        agg_kernel<<<(NN + 7) / 8, 256>>>(l);
    }

    pool_kernel<<<512, 128>>>((const float*)p_h1, batch);
    final_kernel<<<NG, 128>>>(Wlin, blin, out);
}